// round 7
// baseline (speedup 1.0000x reference)
#include <cuda_runtime.h>
#include <math.h>

typedef unsigned long long u64;

#define NTOK 8192
#define HDIM 2048
#define NEXP 32
#define RDIM 16
#define ADIM 32
#define CAP  1024
#define KC   64

// ---------------- static device scratch ------------------------------------
__device__ float d_aw[NEXP];
__device__ int   d_cnt[NEXP];
__device__ int   d_items[NEXP * CAP];           // token*2 + slot
__device__ float d_coef[NTOK * 2];
__device__ float d_Ut[NEXP * RDIM * HDIM];      // 4MB, r-major U

// ---------------- packed f32x2 + cp.async + red helpers ---------------------
__device__ __forceinline__ void fma2(u64 &d, u64 a, u64 b) {
    asm("fma.rn.f32x2 %0, %1, %2, %0;" : "+l"(d) : "l"(a), "l"(b));
}
__device__ __forceinline__ u64 dup2(float a) {
    u64 r; asm("mov.b64 %0, {%1, %1};" : "=l"(r) : "f"(a)); return r;
}
__device__ __forceinline__ float lo32(u64 v) { return __uint_as_float((unsigned)v); }
__device__ __forceinline__ float hi32(u64 v) { return __uint_as_float((unsigned)(v >> 32)); }

__device__ __forceinline__ void cpa16(void* dst, const void* src) {
    unsigned d = (unsigned)__cvta_generic_to_shared(dst);
    asm volatile("cp.async.cg.shared.global [%0], [%1], 16;" :: "r"(d), "l"(src));
}
#define CP_COMMIT()  asm volatile("cp.async.commit_group;")
#define CP_WAIT0()   asm volatile("cp.async.wait_group 0;")
#define CP_WAIT1()   asm volatile("cp.async.wait_group 1;")

__device__ __forceinline__ void red4(float* addr, float x, float y, float z, float w) {
    asm volatile("red.global.add.v4.f32 [%0], {%1, %2, %3, %4};"
                 :: "l"(addr), "f"(x), "f"(y), "f"(z), "f"(w) : "memory");
}

// ============ kernel 0: zero the output ====================================
__global__ __launch_bounds__(256) void zero_kernel(float* __restrict__ out)
{
    int i = blockIdx.x * 256 + threadIdx.x;
    ((float4*)out)[i] = make_float4(0.f, 0.f, 0.f, 0.f);
}

// ============ kernel 1: prep (Ut transpose, aw, counter reset) =============
__global__ __launch_bounds__(256) void prep_kernel(
    const float* __restrict__ U, const float* __restrict__ attr,
    const float* __restrict__ Wa)
{
    __shared__ float ts[RDIM][129];
    int t  = threadIdx.x;
    int s  = blockIdx.x >> 4;
    int k0 = (blockIdx.x & 15) * 128;

    const float* src = U + ((size_t)s * HDIM + k0) * RDIM;
    #pragma unroll
    for (int i = 0; i < 8; i++) {
        int e = t + 256 * i;            // e = kl*16 + r
        ts[e & 15][e >> 4] = src[e];
    }
    __syncthreads();
    #pragma unroll
    for (int i = 0; i < 8; i++) {
        int o = t + 256 * i;            // o = r*128 + kl
        int r = o >> 7, kl = o & 127;
        d_Ut[((size_t)s * RDIM + r) * HDIM + k0 + kl] = ts[r][kl];
    }

    if (blockIdx.x == 0 && t < NEXP) {
        d_cnt[t] = 0;
        float acc = 0.f;
        #pragma unroll
        for (int dd = 0; dd < ADIM; dd++) acc += attr[t * ADIM + dd] * Wa[dd];
        d_aw[t] = 1.f / (1.f + expf(-acc));
    }
}

// ============ kernel 2: router (32 tokens per CTA, 256 CTAs) ===============
#define WSTR 80   // Ws row stride: 20s mod 32 -> conflict-free 8-lane phases
__global__ __launch_bounds__(256) void router_kernel(
    const float* __restrict__ h, const float* __restrict__ Wr)
{
    __shared__ float Hs[2][32][KC + 4];
    __shared__ float Ws[2][32][WSTR];
    __shared__ float scS[32][NEXP + 1];

    int t  = threadIdx.x;
    int tb = blockIdx.x * 32;
    int s  = t & 31;          // lane -> expert
    int tg = t >> 5;          // warp -> 4-token group

    u64 acc[4];
    #pragma unroll
    for (int i = 0; i < 4; i++) acc[i] = 0ull;

    #define R_STAGE(b, kc) {                                                  \
        int k0_ = (kc) * KC;                                                  \
        _Pragma("unroll")                                                     \
        for (int j = 0; j < 2; j++) {                                         \
            int idx = t + 256 * j;                                            \
            int row = idx >> 4, q = idx & 15;                                 \
            cpa16(&Hs[b][row][q * 4],                                         \
                  &h[(size_t)(tb + row) * HDIM + k0_ + q * 4]);               \
            cpa16(&Ws[b][row][q * 4],                                         \
                  &Wr[(size_t)row * HDIM + k0_ + q * 4]);                     \
        }                                                                     \
        CP_COMMIT(); }

    R_STAGE(0, 0);
    int buf = 0;
    for (int kc = 0; kc < HDIM / KC; kc++) {
        if (kc + 1 < HDIM / KC) { R_STAGE(buf ^ 1, kc + 1); CP_WAIT1(); }
        else                    { CP_WAIT0(); }
        __syncthreads();
        const float* Wp = &Ws[buf][s][0];
        const float* Hp = &Hs[buf][tg * 4][0];
        #pragma unroll 4
        for (int kk = 0; kk < KC; kk += 4) {
            ulonglong2 w = *(const ulonglong2*)(Wp + kk);
            #pragma unroll
            for (int i = 0; i < 4; i++) {
                ulonglong2 hh = *(const ulonglong2*)(Hp + i * (KC + 4) + kk);
                fma2(acc[i], hh.x, w.x);
                fma2(acc[i], hh.y, w.y);
            }
        }
        __syncthreads();
        buf ^= 1;
    }
    #pragma unroll
    for (int i = 0; i < 4; i++) scS[tg * 4 + i][s] = lo32(acc[i]) + hi32(acc[i]);
    __syncthreads();

    if (t < 32) {
        int token = tb + t;
        float v1 = -1e30f, v2 = -1e30f; int i1 = 0, i2 = 0;
        #pragma unroll
        for (int ss = 0; ss < NEXP; ss++) {
            float v = scS[t][ss];
            if (v > v1)      { v2 = v1; i2 = i1; v1 = v; i1 = ss; }
            else if (v > v2) { v2 = v;  i2 = ss; }
        }
        float Z = 0.f;
        #pragma unroll
        for (int ss = 0; ss < NEXP; ss++) Z += expf(scS[t][ss] - v1);
        float g1 = 1.f / Z;
        float g2 = expf(v2 - v1) / Z;
        float inv = 1.f / (g1 + g2 + 1e-8f);
        g1 *= inv; g2 *= inv;
        float scale = 0.9f + 0.2f * (g1 * d_aw[i1] + g2 * d_aw[i2]);
        d_coef[token * 2]     = scale * g1;
        d_coef[token * 2 + 1] = scale * g2;
        int p1 = atomicAdd(&d_cnt[i1], 1);
        if (p1 < CAP) d_items[i1 * CAP + p1] = token * 2;
        int p2 = atomicAdd(&d_cnt[i2], 1);
        if (p2 < CAP) d_items[i2 * CAP + p2] = token * 2 + 1;
    }
}

// ============ kernel 3: expert-grouped MoE, 128 assignments/tile ===========
// dynamic smem layout (bytes):
//   [0,512)        itemS  int[128]
//   [512,1024)     coefS  float[128]
//   [1024,9728)    As     float[128][17]
//   [9728,79360)   Hs     float[2][128][68]  (phase 1) | aliased by
//   [9728,43008)   Vs     float[2][16][260]  (phase 2) |
//   [79360,90624)  Uts    float[2][16][88]
#define USTR 88   // 12rq mod 32 -> conflict-free
#define MOE_SMEM 90624

__global__ __launch_bounds__(256) void moe_kernel(
    const float* __restrict__ h, const float* __restrict__ V,
    float* __restrict__ out)
{
    extern __shared__ char sm[];
    int*   itemS = (int*)sm;
    float* coefS = (float*)(sm + 512);
    float* As    = (float*)(sm + 1024);
    float* Hb    = (float*)(sm + 9728);
    float* Vb    = (float*)(sm + 9728);
    float* Ub    = (float*)(sm + 79360);
    #define HS(b,m,q) Hb[(b)*128*68 + (m)*68 + (q)]
    #define US(b,r,q) Ub[(b)*16*USTR + (r)*USTR + (q)]
    #define VS(b,r,q) Vb[(b)*16*260 + (r)*260 + (q)]
    #define AS(m,r)   As[(m)*17 + (r)]

    int t    = threadIdx.x;
    int s    = blockIdx.x >> 3;
    int tile = blockIdx.x & 7;
    int n    = d_cnt[s]; if (n > CAP) n = CAP;
    int base = tile * 128;
    if (base >= n) return;
    int cnt = min(128, n - base);

    if (t < 128) {
        if (t < cnt) {
            int item = d_items[s * CAP + base + t];
            itemS[t] = item;
            coefS[t] = d_coef[item];
        } else { itemS[t] = 0; coefS[t] = 0.f; }
    }
    __syncthreads();

    // ---- phase 1: A[128][16] = gathered H @ Ut[s]^T, coef folded ----------
    #define M_STAGE1(b, kc) {                                                 \
        int k0_ = (kc) * KC;                                                  \
        int row0 = t >> 4, q_ = t & 15;                                       \
        _Pragma("unroll")                                                     \
        for (int p = 0; p < 8; p++) {                                         \
            int row = row0 + 16 * p;                                          \
            int tok = itemS[row] >> 1;                                        \
            cpa16(&HS(b, row, q_ * 4),                                        \
                  &h[(size_t)tok * HDIM + k0_ + q_ * 4]);                     \
        }                                                                     \
        cpa16(&US(b, row0, q_ * 4),                                           \
              &d_Ut[((size_t)s * RDIM + row0) * HDIM + k0_ + q_ * 4]);        \
        CP_COMMIT(); }

    int mg = t >> 3;          // rows mg*4 .. mg*4+3
    int rq = t & 7;           // r = 2*rq, 2*rq+1
    u64 acc[4][2];
    #pragma unroll
    for (int i = 0; i < 4; i++) { acc[i][0] = 0ull; acc[i][1] = 0ull; }

    M_STAGE1(0, 0);
    int buf = 0;
    for (int kc = 0; kc < HDIM / KC; kc++) {
        if (kc + 1 < HDIM / KC) { M_STAGE1(buf ^ 1, kc + 1); CP_WAIT1(); }
        else                    { CP_WAIT0(); }
        __syncthreads();
        const float* Hp = &HS(buf, mg * 4, 0);
        const float* Up = &US(buf, rq * 2, 0);
        #pragma unroll 4
        for (int kk = 0; kk < KC; kk += 4) {
            ulonglong2 u0 = *(const ulonglong2*)(Up + kk);
            ulonglong2 u1 = *(const ulonglong2*)(Up + USTR + kk);
            #pragma unroll
            for (int i = 0; i < 4; i++) {
                ulonglong2 hh = *(const ulonglong2*)(Hp + i * 68 + kk);
                fma2(acc[i][0], hh.x, u0.x); fma2(acc[i][0], hh.y, u0.y);
                fma2(acc[i][1], hh.x, u1.x); fma2(acc[i][1], hh.y, u1.y);
            }
        }
        __syncthreads();
        buf ^= 1;
    }
    #pragma unroll
    for (int i = 0; i < 4; i++) {
        float cf = coefS[mg * 4 + i];
        AS(mg * 4 + i, rq * 2)     = cf * (lo32(acc[i][0]) + hi32(acc[i][0]));
        AS(mg * 4 + i, rq * 2 + 1) = cf * (lo32(acc[i][1]) + hi32(acc[i][1]));
    }
    __syncthreads();

    // ---- phase 2: Out[128][2048] += A @ V[s] via red.global ---------------
    #define M_STAGE2(b, nc) {                                                 \
        _Pragma("unroll")                                                     \
        for (int j = 0; j < 4; j++) {                                         \
            int idx = t + 256 * j;                                            \
            int rr = idx >> 6, q_ = idx & 63;                                 \
            cpa16(&VS(b, rr, q_ * 4),                                         \
                  &V[((size_t)s * RDIM + rr) * HDIM + (nc) * 256 + q_ * 4]);  \
        }                                                                     \
        CP_COMMIT(); }

    int rg = t >> 5;            // warp id -> 8-row group
    int cA = (t & 31) * 4;      // first 4-col quad
    int cB = cA + 128;          // second 4-col quad

    M_STAGE2(0, 0);
    buf = 0;
    for (int nc = 0; nc < HDIM / 256; nc++) {
        if (nc + 1 < HDIM / 256) { M_STAGE2(buf ^ 1, nc + 1); CP_WAIT1(); }
        else                     { CP_WAIT0(); }
        __syncthreads();

        #pragma unroll
        for (int ph = 0; ph < 2; ph++) {
            int rbase = ph * 64 + rg * 8;
            u64 oa[8][4];
            #pragma unroll
            for (int i = 0; i < 8; i++)
                #pragma unroll
                for (int j = 0; j < 4; j++) oa[i][j] = 0ull;

            const float* Vp = &VS(buf, 0, 0);
            #pragma unroll
            for (int r = 0; r < RDIM; r++) {
                ulonglong2 vA = *(const ulonglong2*)(Vp + r * 260 + cA);
                ulonglong2 vB = *(const ulonglong2*)(Vp + r * 260 + cB);
                #pragma unroll
                for (int i = 0; i < 8; i++) {
                    u64 a2 = dup2(AS(rbase + i, r));
                    fma2(oa[i][0], a2, vA.x);
                    fma2(oa[i][1], a2, vA.y);
                    fma2(oa[i][2], a2, vB.x);
                    fma2(oa[i][3], a2, vB.y);
                }
            }
            #pragma unroll
            for (int i = 0; i < 8; i++) {
                int row = rbase + i;
                if (row < cnt) {
                    int token = itemS[row] >> 1;
                    float* dst = out + (size_t)token * HDIM + nc * 256;
                    red4(dst + cA, lo32(oa[i][0]), hi32(oa[i][0]),
                                   lo32(oa[i][1]), hi32(oa[i][1]));
                    red4(dst + cB, lo32(oa[i][2]), hi32(oa[i][2]),
                                   lo32(oa[i][3]), hi32(oa[i][3]));
                }
            }
        }
        __syncthreads();
        buf ^= 1;
    }
}

// ===========================================================================
extern "C" void kernel_launch(void* const* d_in, const int* in_sizes, int n_in,
                              void* d_out, int out_size)
{
    const float* h    = (const float*)d_in[0];
    const float* Wr   = (const float*)d_in[1];
    const float* U    = (const float*)d_in[2];
    const float* V    = (const float*)d_in[3];
    const float* attr = (const float*)d_in[4];
    const float* Wa   = (const float*)d_in[5];
    float* out = (float*)d_out;

    static int smem_set = 0;
    if (!smem_set) {
        cudaFuncSetAttribute(moe_kernel,
            cudaFuncAttributeMaxDynamicSharedMemorySize, MOE_SMEM);
        smem_set = 1;
    }

    zero_kernel<<<NTOK * HDIM / 4 / 256, 256>>>(out);
    prep_kernel<<<512, 256>>>(U, attr, Wa);
    router_kernel<<<NTOK / 32, 256>>>(h, Wr);
    moe_kernel<<<NEXP * (CAP / 128), 256, MOE_SMEM>>>(h, V, out);
}

// round 12
// speedup vs baseline: 1.3383x; 1.3383x over previous
#include <cuda_runtime.h>
#include <math.h>

typedef unsigned long long u64;

#define NTOK 8192
#define HDIM 2048
#define NEXP 32
#define RDIM 16
#define ADIM 32
#define CAP  1024
#define KC   64

// ---------------- static device scratch ------------------------------------
__device__ float d_aw[NEXP];
__device__ int   d_cnt[NEXP];
__device__ int   d_items[NEXP * CAP];           // token*2 + slot
__device__ float d_coef[NTOK * 2];
__device__ float d_Ut[NEXP * RDIM * HDIM];      // 4MB, r-major U
__device__ float d_A[NEXP * CAP * RDIM];        // 2MB, coef-folded hU
__device__ float d_p1[NTOK * HDIM];             // 64MB slot-1 partials

// ---------------- packed f32x2 + cp.async helpers ---------------------------
__device__ __forceinline__ void fma2(u64 &d, u64 a, u64 b) {
    asm("fma.rn.f32x2 %0, %1, %2, %0;" : "+l"(d) : "l"(a), "l"(b));
}
__device__ __forceinline__ u64 dup2(float a) {
    u64 r; asm("mov.b64 %0, {%1, %1};" : "=l"(r) : "f"(a)); return r;
}
__device__ __forceinline__ float lo32(u64 v) { return __uint_as_float((unsigned)v); }
__device__ __forceinline__ float hi32(u64 v) { return __uint_as_float((unsigned)(v >> 32)); }

__device__ __forceinline__ void cpa16(void* dst, const void* src) {
    unsigned d = (unsigned)__cvta_generic_to_shared(dst);
    asm volatile("cp.async.cg.shared.global [%0], [%1], 16;" :: "r"(d), "l"(src));
}
#define CP_COMMIT()  asm volatile("cp.async.commit_group;")
#define CP_WAIT0()   asm volatile("cp.async.wait_group 0;")
#define CP_WAIT1()   asm volatile("cp.async.wait_group 1;")

// ============ kernel 1: prep (Ut transpose, aw, counter reset) =============
__global__ __launch_bounds__(256) void prep_kernel(
    const float* __restrict__ U, const float* __restrict__ attr,
    const float* __restrict__ Wa)
{
    __shared__ float ts[RDIM][129];
    int t  = threadIdx.x;
    int s  = blockIdx.x >> 4;
    int k0 = (blockIdx.x & 15) * 128;

    const float* src = U + ((size_t)s * HDIM + k0) * RDIM;
    #pragma unroll
    for (int i = 0; i < 8; i++) {
        int e = t + 256 * i;            // e = kl*16 + r
        ts[e & 15][e >> 4] = src[e];
    }
    __syncthreads();
    #pragma unroll
    for (int i = 0; i < 8; i++) {
        int o = t + 256 * i;            // o = r*128 + kl
        int r = o >> 7, kl = o & 127;
        d_Ut[((size_t)s * RDIM + r) * HDIM + k0 + kl] = ts[r][kl];
    }

    if (blockIdx.x == 0 && t < NEXP) {
        d_cnt[t] = 0;
        float acc = 0.f;
        #pragma unroll
        for (int dd = 0; dd < ADIM; dd++) acc += attr[t * ADIM + dd] * Wa[dd];
        d_aw[t] = 1.f / (1.f + expf(-acc));
    }
}

// ============ kernel 2: router (32 tokens per CTA, 256 CTAs) ===============
__global__ __launch_bounds__(256) void router_kernel(
    const float* __restrict__ h, const float* __restrict__ Wr)
{
    __shared__ float Hs[2][32][KC + 4];     // 272B rows: 16B-aligned, odd 16B units
    __shared__ float Ws[2][32][KC + 4];
    __shared__ float scS[32][NEXP + 1];

    int t  = threadIdx.x;
    int tb = blockIdx.x * 32;
    int s  = t & 31;          // lane -> expert
    int tg = t >> 5;          // warp -> 4-token group

    u64 acc[4];
    #pragma unroll
    for (int i = 0; i < 4; i++) acc[i] = 0ull;

    #define R_STAGE(b, kc) {                                                  \
        int k0_ = (kc) * KC;                                                  \
        _Pragma("unroll")                                                     \
        for (int j = 0; j < 2; j++) {                                         \
            int idx = t + 256 * j;                                            \
            int row = idx >> 4, q = idx & 15;                                 \
            cpa16(&Hs[b][row][q * 4],                                         \
                  &h[(size_t)(tb + row) * HDIM + k0_ + q * 4]);               \
            cpa16(&Ws[b][row][q * 4],                                         \
                  &Wr[(size_t)row * HDIM + k0_ + q * 4]);                     \
        }                                                                     \
        CP_COMMIT(); }

    R_STAGE(0, 0);
    int buf = 0;
    for (int kc = 0; kc < HDIM / KC; kc++) {
        if (kc + 1 < HDIM / KC) { R_STAGE(buf ^ 1, kc + 1); CP_WAIT1(); }
        else                    { CP_WAIT0(); }
        __syncthreads();
        const float* Wp = &Ws[buf][s][0];
        const float* Hp = &Hs[buf][tg * 4][0];
        #pragma unroll 4
        for (int kk = 0; kk < KC; kk += 4) {
            ulonglong2 w = *(const ulonglong2*)(Wp + kk);
            #pragma unroll
            for (int i = 0; i < 4; i++) {
                ulonglong2 hh = *(const ulonglong2*)(Hp + i * (KC + 4) + kk);
                fma2(acc[i], hh.x, w.x);
                fma2(acc[i], hh.y, w.y);
            }
        }
        __syncthreads();
        buf ^= 1;
    }
    #pragma unroll
    for (int i = 0; i < 4; i++) scS[tg * 4 + i][s] = lo32(acc[i]) + hi32(acc[i]);
    __syncthreads();

    if (t < 32) {
        int token = tb + t;
        float v1 = -1e30f, v2 = -1e30f; int i1 = 0, i2 = 0;
        #pragma unroll
        for (int ss = 0; ss < NEXP; ss++) {
            float v = scS[t][ss];
            if (v > v1)      { v2 = v1; i2 = i1; v1 = v; i1 = ss; }
            else if (v > v2) { v2 = v;  i2 = ss; }
        }
        float Z = 0.f;
        #pragma unroll
        for (int ss = 0; ss < NEXP; ss++) Z += expf(scS[t][ss] - v1);
        float g1 = 1.f / Z;
        float g2 = expf(v2 - v1) / Z;
        float inv = 1.f / (g1 + g2 + 1e-8f);
        g1 *= inv; g2 *= inv;
        float scale = 0.9f + 0.2f * (g1 * d_aw[i1] + g2 * d_aw[i2]);
        d_coef[token * 2]     = scale * g1;
        d_coef[token * 2 + 1] = scale * g2;
        int p1 = atomicAdd(&d_cnt[i1], 1);
        if (p1 < CAP) d_items[i1 * CAP + p1] = token * 2;
        int p2 = atomicAdd(&d_cnt[i2], 1);
        if (p2 < CAP) d_items[i2 * CAP + p2] = token * 2 + 1;
    }
}

// ============ kernel 3a: moe1 — A[assign][16] = gathered H @ Ut[s]^T =======
// 64-row tiles, grid = 32*16 = 512. Static smem ~44KB, 2 CTAs/SM.
__global__ __launch_bounds__(256, 2) void moe1_kernel(const float* __restrict__ h)
{
    __shared__ int   itemS[64];
    __shared__ float coefS[64];
    __shared__ float Hs[2][64][KC + 4];
    __shared__ float Us[2][16][KC + 4];

    int t    = threadIdx.x;
    int s    = blockIdx.x >> 4;
    int tile = blockIdx.x & 15;
    int n    = min(d_cnt[s], CAP);
    int base = tile * 64;
    if (base >= n) return;
    int cnt = min(64, n - base);

    if (t < 64) {
        if (t < cnt) {
            int item = d_items[s * CAP + base + t];
            itemS[t] = item;
            coefS[t] = d_coef[item];
        } else { itemS[t] = 0; coefS[t] = 0.f; }
    }
    __syncthreads();

    #define M1_STAGE(b, kc) {                                                 \
        int k0_ = (kc) * KC;                                                  \
        int row0 = t >> 4, q_ = t & 15;                                       \
        _Pragma("unroll")                                                     \
        for (int p = 0; p < 4; p++) {                                         \
            int row = row0 + 16 * p;                                          \
            int tok = itemS[row] >> 1;                                        \
            cpa16(&Hs[b][row][q_ * 4],                                        \
                  &h[(size_t)tok * HDIM + k0_ + q_ * 4]);                     \
        }                                                                     \
        cpa16(&Us[b][row0][q_ * 4],                                           \
              &d_Ut[((size_t)s * RDIM + row0) * HDIM + k0_ + q_ * 4]);        \
        CP_COMMIT(); }

    int mg = t >> 3;          // rows mg*2, mg*2+1
    int rq = t & 7;           // r = rq and rq+8 (17x16B row step: odd)
    u64 a00 = 0, a01 = 0, a10 = 0, a11 = 0;   // [row][r]

    M1_STAGE(0, 0);
    int buf = 0;
    for (int kc = 0; kc < HDIM / KC; kc++) {
        if (kc + 1 < HDIM / KC) { M1_STAGE(buf ^ 1, kc + 1); CP_WAIT1(); }
        else                    { CP_WAIT0(); }
        __syncthreads();
        const float* Hp0 = &Hs[buf][mg * 2][0];
        const float* Hp1 = Hp0 + (KC + 4);
        const float* Up0 = &Us[buf][rq][0];
        const float* Up1 = &Us[buf][rq + 8][0];
        #pragma unroll 4
        for (int kk = 0; kk < KC; kk += 4) {
            ulonglong2 u0 = *(const ulonglong2*)(Up0 + kk);
            ulonglong2 u1 = *(const ulonglong2*)(Up1 + kk);
            ulonglong2 h0 = *(const ulonglong2*)(Hp0 + kk);
            ulonglong2 h1 = *(const ulonglong2*)(Hp1 + kk);
            fma2(a00, h0.x, u0.x); fma2(a00, h0.y, u0.y);
            fma2(a01, h0.x, u1.x); fma2(a01, h0.y, u1.y);
            fma2(a10, h1.x, u0.x); fma2(a10, h1.y, u0.y);
            fma2(a11, h1.x, u1.x); fma2(a11, h1.y, u1.y);
        }
        __syncthreads();
        buf ^= 1;
    }
    {
        float cf0 = coefS[mg * 2], cf1 = coefS[mg * 2 + 1];
        float* A0 = &d_A[((size_t)(s * CAP + base + mg * 2)) * RDIM];
        float* A1 = A0 + RDIM;
        A0[rq]     = cf0 * (lo32(a00) + hi32(a00));
        A0[rq + 8] = cf0 * (lo32(a01) + hi32(a01));
        A1[rq]     = cf1 * (lo32(a10) + hi32(a10));
        A1[rq + 8] = cf1 * (lo32(a11) + hi32(a11));
    }
}

// ============ kernel 3b: moe2 — Out[64][128] = A-tile @ V-chunk ============
// grid = 32 experts x 16 row-tiles x 16 col-chunks = 8192 CTAs (~half active)
__global__ __launch_bounds__(256, 3) void moe2_kernel(
    const float* __restrict__ V, float* __restrict__ out)
{
    __shared__ int   itemS[64];
    __shared__ float As[64][16];       // 64B rows -> cp.async dst always 16B-aligned;
                                       // reads are warp-uniform (broadcast), no conflicts
    __shared__ float Vs[16][132];      // 528B rows = 33x16B (odd) -> conflict-free

    int t  = threadIdx.x;
    int s  = blockIdx.x >> 8;
    int rt = (blockIdx.x >> 4) & 15;
    int cc = blockIdx.x & 15;
    int n    = min(d_cnt[s], CAP);
    int base = rt * 64;
    if (base >= n) return;
    int cnt = min(64, n - base);

    if (t < 64) itemS[t] = (t < cnt) ? d_items[s * CAP + base + t] : -1;
    {   // stage A: 64 rows x 4 quads
        int m = t >> 2, q = t & 3;
        cpa16(&As[m][q * 4], &d_A[((size_t)(s * CAP + base + m)) * RDIM + q * 4]);
    }
    {   // stage V chunk: 16 r x 32 quads
        #pragma unroll
        for (int j = 0; j < 2; j++) {
            int idx = t + 256 * j;
            int rr = idx >> 5, q = idx & 31;
            cpa16(&Vs[rr][q * 4],
                  &V[((size_t)s * RDIM + rr) * HDIM + cc * 128 + q * 4]);
        }
    }
    CP_COMMIT(); CP_WAIT0();
    __syncthreads();

    int rg = t >> 5;            // warp -> 8-row group
    int c0 = (t & 31) * 4;      // 4-col quad per lane
    u64 oa[8][2];
    #pragma unroll
    for (int i = 0; i < 8; i++) { oa[i][0] = 0ull; oa[i][1] = 0ull; }

    #pragma unroll
    for (int r = 0; r < RDIM; r++) {
        ulonglong2 v = *(const ulonglong2*)&Vs[r][c0];
        #pragma unroll
        for (int i = 0; i < 8; i++) {
            u64 a2 = dup2(As[rg * 8 + i][r]);
            fma2(oa[i][0], a2, v.x);
            fma2(oa[i][1], a2, v.y);
        }
    }
    #pragma unroll
    for (int i = 0; i < 8; i++) {
        int row = rg * 8 + i;
        if (row < cnt) {
            int item  = itemS[row];
            int token = item >> 1;
            float* dst = ((item & 1) ? d_p1 : out)
                         + (size_t)token * HDIM + cc * 128 + c0;
            *(float4*)dst = make_float4(lo32(oa[i][0]), hi32(oa[i][0]),
                                        lo32(oa[i][1]), hi32(oa[i][1]));
        }
    }
}

// ============ kernel 4: combine slot-0 (out) + slot-1 (d_p1) ===============
__global__ __launch_bounds__(256) void combine_kernel(float* __restrict__ out)
{
    int i = blockIdx.x * 256 + threadIdx.x;
    float4 a = ((const float4*)out)[i];
    float4 b = ((const float4*)d_p1)[i];
    a.x += b.x; a.y += b.y; a.z += b.z; a.w += b.w;
    ((float4*)out)[i] = a;
}

// ===========================================================================
extern "C" void kernel_launch(void* const* d_in, const int* in_sizes, int n_in,
                              void* d_out, int out_size)
{
    const float* h    = (const float*)d_in[0];
    const float* Wr   = (const float*)d_in[1];
    const float* U    = (const float*)d_in[2];
    const float* V    = (const float*)d_in[3];
    const float* attr = (const float*)d_in[4];
    const float* Wa   = (const float*)d_in[5];
    float* out = (float*)d_out;

    prep_kernel<<<512, 256>>>(U, attr, Wa);
    router_kernel<<<NTOK / 32, 256>>>(h, Wr);
    moe1_kernel<<<NEXP * 16, 256>>>(h);
    moe2_kernel<<<NEXP * 16 * 16, 256>>>(V, out);
    combine_kernel<<<NTOK * HDIM / 4 / 256, 256>>>(out);
}